// round 14
// baseline (speedup 1.0000x reference)
#include <cuda_runtime.h>
#include <cstdint>

// SpatialTransformer bilinear grid sample — bit-exact vs reference (rel_err 0.0
// through R11). LOCKED arithmetic: fp32 serial-K FMA-chain einsum, unfused
// pointwise, exact reference association. f32x2 is BANNED (R12/R13 bisect:
// not bit-identical to scalar rn).
//
// R14: remap 1 thread = 1 whole pixel (16 ch as 4 unrolled float4 quads),
// 32 pixels/warp. Coordinate chain issue cost 6.25 -> ~1.6 instr/pixel
// (was computed redundantly by 4 lanes/pixel). ~14.75 -> ~6.8 issued
// instr/pixel. Bytes/sectors unchanged. All pieces R11-proven.

#define ST_B 16
#define ST_H 512
#define ST_W 512
#define ST_C 16
#define ST_HW (ST_H * ST_W)        // 262144 = 2^18
#define ST_LOG_W 9
#define ST_LOG_HW 18

// Predicated 128-bit load (R11-proven): if pred, v = *p; else keep fallback.
// Predicated-off lanes generate no L1 traffic; no branch instructions.
__device__ __forceinline__ void pld128(float4& v, const float* p, int pred) {
    asm("{\n\t"
        ".reg .pred q;\n\t"
        "setp.ne.s32 q, %5, 0;\n\t"
        "@q ld.global.nc.v4.f32 {%0,%1,%2,%3}, [%4];\n\t"
        "}"
        : "+f"(v.x), "+f"(v.y), "+f"(v.z), "+f"(v.w)
        : "l"(p), "r"(pred));
}

__global__ __launch_bounds__(256)
void st_bilinear_kernel(const float* __restrict__ images,
                        const float* __restrict__ theta,
                        float* __restrict__ out)
{
    const uint32_t pix = blockIdx.x * 256u + threadIdx.x;   // one pixel per thread

    const uint32_t b  = pix >> ST_LOG_HW;
    const uint32_t yo = (pix >> ST_LOG_W) & (ST_H - 1);
    const uint32_t xo = pix & (ST_W - 1);

    // theta (b,2,3): 3x float2 (8B-aligned: b*24B); b warp-uniform (32 | 2^18)
    const float* th = theta + b * 6;
    const float2 ta = __ldg((const float2*)(th + 0));
    const float2 tb = __ldg((const float2*)(th + 2));
    const float2 tc = __ldg((const float2*)(th + 4));
    const float t00 = ta.x, t01 = ta.y, t02 = tb.x;
    const float t10 = tb.y, t11 = tc.x, t12 = tc.y;

    const float xof = (float)xo;
    const float yof = (float)yo;

    // --- einsum: fp32 serial-K FMA chain (LOCKED, R11 verbatim) ------------
    float xn = __fadd_rn(__fmaf_rn(t01, yof, __fmul_rn(t00, xof)), t02);
    float yn = __fadd_rn(__fmaf_rn(t11, yof, __fmul_rn(t10, xof)), t12);

    // --- affine: 0.5*((x+1)*W - 1), unfused (LOCKED) -----------------------
    float x = __fmul_rn(0.5f, __fsub_rn(__fmul_rn(__fadd_rn(xn, 1.0f), (float)ST_W), 1.0f));
    float y = __fmul_rn(0.5f, __fsub_rn(__fmul_rn(__fadd_rn(yn, 1.0f), (float)ST_H), 1.0f));

    // (int)floorf == __float2int_rd for our range (R11-verified)
    const int xf = __float2int_rd(x);
    const int yf = __float2int_rd(y);
    const int x0 = min(max(xf,     0), ST_W - 1);
    const int x1 = min(max(xf + 1, 0), ST_W - 1);
    const int y0 = min(max(yf,     0), ST_H - 1);
    const int y1 = min(max(yf + 1, 0), ST_H - 1);

    const float x0f = (float)x0, x1f = (float)x1;
    const float y0f = (float)y0, y1f = (float)y1;

    const float dx1 = __fsub_rn(x1f, x);
    const float dx0 = __fsub_rn(x, x0f);
    const float dy1 = __fsub_rn(y1f, y);
    const float dy0 = __fsub_rn(y, y0f);

    const float wa = __fmul_rn(dx1, dy1);  // * p00 (y0,x0)
    const float wb = __fmul_rn(dx1, dy0);  // * p01 (y1,x0)
    const float wc = __fmul_rn(dx0, dy1);  // * p10 (y0,x1)
    const float wd = __fmul_rn(dx0, dy0);  // * p11 (y1,x1)

    const int lx = (x1 != x0);
    const int ly = (y1 != y0);
    const int lxy = lx & ly;

    const float* img = images + (size_t)b * (ST_HW * ST_C);
    const uint32_t off00 = ((((uint32_t)y0 << ST_LOG_W) + (uint32_t)x0) << 4);
    const float* p00p = img + off00;
    float* outp = out + (size_t)pix * ST_C;

    // 16 channels as 4 unrolled float4 quads; LOCKED interp per channel.
#pragma unroll
    for (uint32_t q = 0; q < 4; q++) {
        const uint32_t co = q * 4u;

        const float4 p00 = __ldg((const float4*)(p00p + co));

        float4 p10 = p00;                       // fallback: x collapsed
        pld128(p10, p00p + co + ST_C, lx);

        float4 p01 = p00;                       // fallback: y collapsed
        pld128(p01, p00p + co + (ST_W * ST_C), ly);

        float4 p11 = lx ? p10 : p01;            // collapsed reuse (bit-identical)
        pld128(p11, p00p + co + (ST_W * ST_C) + ST_C, lxy);

        // ((wa*p00 + wb*p01) + wc*p10) + wd*p11, individually rounded (LOCKED)
        float4 r;
        r.x = __fadd_rn(__fadd_rn(__fadd_rn(__fmul_rn(wa, p00.x), __fmul_rn(wb, p01.x)),
                                  __fmul_rn(wc, p10.x)), __fmul_rn(wd, p11.x));
        r.y = __fadd_rn(__fadd_rn(__fadd_rn(__fmul_rn(wa, p00.y), __fmul_rn(wb, p01.y)),
                                  __fmul_rn(wc, p10.y)), __fmul_rn(wd, p11.y));
        r.z = __fadd_rn(__fadd_rn(__fadd_rn(__fmul_rn(wa, p00.z), __fmul_rn(wb, p01.z)),
                                  __fmul_rn(wc, p10.z)), __fmul_rn(wd, p11.z));
        r.w = __fadd_rn(__fadd_rn(__fadd_rn(__fmul_rn(wa, p00.w), __fmul_rn(wb, p01.w)),
                                  __fmul_rn(wc, p10.w)), __fmul_rn(wd, p11.w));

        *((float4*)(outp + co)) = r;
    }
}

extern "C" void kernel_launch(void* const* d_in, const int* in_sizes, int n_in,
                              void* d_out, int out_size)
{
    const float* images = (const float*)d_in[0];
    const float* theta  = (const float*)d_in[1];
    if (n_in >= 2 && in_sizes[0] < in_sizes[1]) {   // theta is the 96-elem buffer
        images = (const float*)d_in[1];
        theta  = (const float*)d_in[0];
    }
    float* out = (float*)d_out;

    // one thread per pixel: B*H*W = 4,194,304 threads -> 16384 blocks of 256
    const uint32_t total  = (uint32_t)ST_B * ST_HW;
    const uint32_t blocks = total / 256u;
    st_bilinear_kernel<<<blocks, 256>>>(images, theta, out);
}

// round 15
// speedup vs baseline: 1.6671x; 1.6671x over previous
#include <cuda_runtime.h>
#include <cstdint>

// SpatialTransformer bilinear grid sample — bit-exact vs reference (rel_err 0.0
// through R11). LOCKED arithmetic: fp32 serial-K FMA-chain einsum, unfused
// pointwise, exact reference association. f32x2 BANNED (R12/13). 1-thread-per-
// pixel mapping BANNED (R14: kills gather coalescing).
//
// R15: shuffle-amortized coordinates. Each lane runs the LOCKED chain for its
// OWN pixel (warp = 32 consecutive-x pixels, same batch); results (wa,wb,wc,wd,
// offp=(pix00<<4)|lx|(ly<<1)) are broadcast via 5 shfl per 8-pixel group. The
// gather/interp/store stage is R11-verbatim 4-lanes-per-pixel (coalesced).
// Chain cost 6.25 -> ~1.7 instr/pixel; total ~14.75 -> ~7.8.

#define ST_B 16
#define ST_H 512
#define ST_W 512
#define ST_C 16
#define ST_HW (ST_H * ST_W)        // 262144 = 2^18
#define ST_LOG_W 9
#define ST_LOG_HW 18

// Predicated 128-bit load (R11-proven): if pred, v = *p; else keep fallback.
__device__ __forceinline__ void pld128(float4& v, const float* p, int pred) {
    asm("{\n\t"
        ".reg .pred q;\n\t"
        "setp.ne.s32 q, %5, 0;\n\t"
        "@q ld.global.nc.v4.f32 {%0,%1,%2,%3}, [%4];\n\t"
        "}"
        : "+f"(v.x), "+f"(v.y), "+f"(v.z), "+f"(v.w)
        : "l"(p), "r"(pred));
}

__global__ __launch_bounds__(256)
void st_bilinear_kernel(const float* __restrict__ images,
                        const float* __restrict__ theta,
                        float* __restrict__ out)
{
    const uint32_t lane      = threadIdx.x & 31u;
    const uint32_t warp_base = blockIdx.x * 256u + (threadIdx.x & ~31u); // pixel of lane 0
    const uint32_t mypix     = warp_base + lane;      // pixel whose chain THIS lane computes

    const uint32_t b  = mypix >> ST_LOG_HW;           // warp-uniform (32 | 2^18)
    const uint32_t yo = (mypix >> ST_LOG_W) & (ST_H - 1);
    const uint32_t xo = mypix & (ST_W - 1);

    // theta (b,2,3): 3x float2 (8B-aligned)
    const float* th = theta + b * 6;
    const float2 ta = __ldg((const float2*)(th + 0));
    const float2 tb = __ldg((const float2*)(th + 2));
    const float2 tc = __ldg((const float2*)(th + 4));
    const float t00 = ta.x, t01 = ta.y, t02 = tb.x;
    const float t10 = tb.y, t11 = tc.x, t12 = tc.y;

    const float xof = (float)xo;
    const float yof = (float)yo;

    // --- einsum: fp32 serial-K FMA chain (LOCKED, R11 verbatim) ------------
    float xn = __fadd_rn(__fmaf_rn(t01, yof, __fmul_rn(t00, xof)), t02);
    float yn = __fadd_rn(__fmaf_rn(t11, yof, __fmul_rn(t10, xof)), t12);

    // --- affine: 0.5*((x+1)*W - 1), unfused (LOCKED) -----------------------
    float x = __fmul_rn(0.5f, __fsub_rn(__fmul_rn(__fadd_rn(xn, 1.0f), (float)ST_W), 1.0f));
    float y = __fmul_rn(0.5f, __fsub_rn(__fmul_rn(__fadd_rn(yn, 1.0f), (float)ST_H), 1.0f));

    const int xf = __float2int_rd(x);                 // == (int)floorf (R11-verified)
    const int yf = __float2int_rd(y);
    const int x0 = min(max(xf,     0), ST_W - 1);
    const int x1 = min(max(xf + 1, 0), ST_W - 1);
    const int y0 = min(max(yf,     0), ST_H - 1);
    const int y1 = min(max(yf + 1, 0), ST_H - 1);

    const float x0f = (float)x0, x1f = (float)x1;
    const float y0f = (float)y0, y1f = (float)y1;

    const float dx1 = __fsub_rn(x1f, x);
    const float dx0 = __fsub_rn(x, x0f);
    const float dy1 = __fsub_rn(y1f, y);
    const float dy0 = __fsub_rn(y, y0f);

    const float wa = __fmul_rn(dx1, dy1);  // * p00 (y0,x0)
    const float wb = __fmul_rn(dx1, dy0);  // * p01 (y1,x0)
    const float wc = __fmul_rn(dx0, dy1);  // * p10 (y0,x1)
    const float wd = __fmul_rn(dx0, dy0);  // * p11 (y1,x1)

    // pack: offset-with-flags. pix00<<4 leaves bits 0..3 clear.
    const uint32_t offp = ((((uint32_t)y0 << ST_LOG_W) + (uint32_t)x0) << 4)
                        | (uint32_t)(x1 != x0) | ((uint32_t)(y1 != y0) << 1);

    const float* img = images + (size_t)b * (ST_HW * ST_C);
    const uint32_t co      = (lane & 3u) * 4u;        // channel quad for stage 2
    const uint32_t sub     = lane >> 2;               // pixel-within-group (0..7)
    float* outw = out + (size_t)warp_base * ST_C;     // warp's output base

    // --- stage 2: 4 groups of 8 pixels, R11-verbatim gather/interp ---------
#pragma unroll
    for (uint32_t i = 0; i < 4; i++) {
        const uint32_t src = i * 8u + sub;            // lane holding this pixel's chain

        const float Wa = __shfl_sync(0xffffffffu, wa, src);
        const float Wb = __shfl_sync(0xffffffffu, wb, src);
        const float Wc = __shfl_sync(0xffffffffu, wc, src);
        const float Wd = __shfl_sync(0xffffffffu, wd, src);
        const uint32_t op = __shfl_sync(0xffffffffu, offp, src);

        const int lx  = (int)(op & 1u);
        const int ly  = (int)((op >> 1) & 1u);
        const int lxy = lx & ly;
        const float* p00p = img + ((op & ~0xFu) + co);

        const float4 p00 = __ldg((const float4*)p00p);

        float4 p10 = p00;                              // fallback: x collapsed
        pld128(p10, p00p + ST_C, lx);

        float4 p01 = p00;                              // fallback: y collapsed
        pld128(p01, p00p + (ST_W * ST_C), ly);

        float4 p11 = lx ? p10 : p01;                   // collapsed reuse
        pld128(p11, p00p + (ST_W * ST_C) + ST_C, lxy);

        // ((wa*p00 + wb*p01) + wc*p10) + wd*p11, individually rounded (LOCKED)
        float4 r;
        r.x = __fadd_rn(__fadd_rn(__fadd_rn(__fmul_rn(Wa, p00.x), __fmul_rn(Wb, p01.x)),
                                  __fmul_rn(Wc, p10.x)), __fmul_rn(Wd, p11.x));
        r.y = __fadd_rn(__fadd_rn(__fadd_rn(__fmul_rn(Wa, p00.y), __fmul_rn(Wb, p01.y)),
                                  __fmul_rn(Wc, p10.y)), __fmul_rn(Wd, p11.y));
        r.z = __fadd_rn(__fadd_rn(__fadd_rn(__fmul_rn(Wa, p00.z), __fmul_rn(Wb, p01.z)),
                                  __fmul_rn(Wc, p10.z)), __fmul_rn(Wd, p11.z));
        r.w = __fadd_rn(__fadd_rn(__fadd_rn(__fmul_rn(Wa, p00.w), __fmul_rn(Wb, p01.w)),
                                  __fmul_rn(Wc, p10.w)), __fmul_rn(Wd, p11.w));

        *((float4*)(outw + ((i * 8u + sub) * ST_C + co))) = r;
    }
}

extern "C" void kernel_launch(void* const* d_in, const int* in_sizes, int n_in,
                              void* d_out, int out_size)
{
    const float* images = (const float*)d_in[0];
    const float* theta  = (const float*)d_in[1];
    if (n_in >= 2 && in_sizes[0] < in_sizes[1]) {   // theta is the 96-elem buffer
        images = (const float*)d_in[1];
        theta  = (const float*)d_in[0];
    }
    float* out = (float*)d_out;

    // one thread per pixel-chain: B*H*W = 4,194,304 -> 16384 blocks of 256;
    // each warp processes its 32 pixels in 4 groups of 8.
    const uint32_t total  = (uint32_t)ST_B * ST_HW;
    const uint32_t blocks = total / 256u;
    st_bilinear_kernel<<<blocks, 256>>>(images, theta, out);
}